// round 16
// baseline (speedup 1.0000x reference)
#include <cuda_runtime.h>
#include <cuda_fp16.h>

// Fisher-Kolmogorov rollout. R16 = R15 (one-barrier fused step-pair, dr in
// smem) + CTA-uniform interior fast path in phase 1: 77% of CTAs skip all
// boundary predicates/selects. fp16 {D,rho}, PDL, pair0 packs dr.

#define W        128
#define BATCH    2
#define SUBSTEPS 10
#define MAX_DAYS 4
#define NPAIRS   (SUBSTEPS * MAX_DAYS / 2)   // 20
#define PPD      (SUBSTEPS / 2)              // 5 pairs per day
#define MICRO_DT 0.1f

#define VOL  ((size_t)W * W * W)
#define NTOT (BATCH * VOL)

// smem: mids 100 rows x 512B, then dr 64 rows x 512B
#define SM_MID_FLOATS (100 * 128)
#define SMEM_BYTES    ((100 + 64) * 128 * 4)   // 83968

__device__ float g_buf0[NTOT];
__device__ float g_buf1[NTOT];
__device__ __half2 g_dr[NTOT];               // {D, rho} per point (16 MB)

struct __align__(16) H24 { __half2 h[4]; };

__device__ __forceinline__ float4 f4ld(const float* p) {
    return *reinterpret_cast<const float4*>(p);
}
__device__ __forceinline__ void f4st(float* p, float4 v) {
    *reinterpret_cast<float4*>(p) = v;
}

__device__ __forceinline__ void fk_comp(float& o, float c, float nb2,
                                        float nb4, __half2 drh)
{
    const float2 d2 = __half22float2(drh);    // x=D, y=rho
    const float lap = nb2 + nb4 - 6.0f * c;
    o = c + MICRO_DT * (d2.x * lap + d2.y * c * (1.0f - c));
}

__device__ __forceinline__ float4 fk_point(float4 c, float4 ym, float4 yp,
                                           float4 zm, float4 zp,
                                           float lf, float rt, H24 q)
{
    float4 o;
    fk_comp(o.x, c.x, lf  + c.y, ym.x + yp.x + zm.x + zp.x, q.h[0]);
    fk_comp(o.y, c.y, c.x + c.z, ym.y + yp.y + zm.y + zp.y, q.h[1]);
    fk_comp(o.z, c.z, c.y + c.w, ym.z + yp.z + zm.z + zp.z, q.h[2]);
    fk_comp(o.w, c.w, c.z + rt,  ym.w + yp.w + zm.w + zp.w, q.h[3]);
    return o;
}

__device__ __forceinline__ float4 clip01(float4 v)
{
    v.x = fminf(fmaxf(v.x, 0.f), 1.f);
    v.y = fminf(fmaxf(v.y, 0.f), 1.f);
    v.z = fminf(fmaxf(v.z, 0.f), 1.f);
    v.w = fminf(fmaxf(v.w, 0.f), 1.f);
    return v;
}

__device__ __forceinline__ H24 pack_dr(float4 d, float4 r)
{
    H24 q;
    q.h[0] = __floats2half2_rn(d.x, r.x);
    q.h[1] = __floats2half2_rn(d.y, r.y);
    q.h[2] = __floats2half2_rn(d.z, r.z);
    q.h[3] = __floats2half2_rn(d.w, r.w);
    return q;
}

__device__ __forceinline__ void xhalo(float4 u, int tx, float& lf, float& rt)
{
    lf = __shfl_up_sync(0xffffffffu, u.w, 1);
    rt = __shfl_down_sync(0xffffffffu, u.x, 1);
    if (tx == 0)  lf = 0.f;
    if (tx == 31) rt = 0.f;
}

// Phase 1 for regular pairs. INTERIOR=true: no bounds checks anywhere.
template <bool INTERIOR>
__device__ __forceinline__ void pair_phase1(
    const float* __restrict__ usrc, const __half2* __restrict__ dr,
    float* __restrict__ smid, float* __restrict__ sdr,
    size_t bb, int y0, int zb, int tx, int tid16, int x4)
{
    const size_t PL = (size_t)W * W;
    const float4 zero4 = make_float4(0.f, 0.f, 0.f, 0.f);

    #pragma unroll
    for (int k = 0; k < 7; ++k) {
        const int idx = tid16 + k * 16;
        if (k == 6 && tid16 >= 4) break;      // rows 96..99 only
        const int p = idx / 10;               // plane zb-1+p
        const int r = idx - p * 10;           // row   y0-1+r
        const int gy = y0 - 1 + r;
        const int gz = zb - 1 + p;
        const size_t bm = bb + ((size_t)gz * W + gy) * W + x4;
        float4 m;
        if (INTERIOR) {
            const float4 c   = f4ld(usrc + bm);
            const float4 ymv = f4ld(usrc + bm - W);
            const float4 ypv = f4ld(usrc + bm + W);
            const float4 zmv = f4ld(usrc + bm - PL);
            const float4 zpv = f4ld(usrc + bm + PL);
            const H24 q = *reinterpret_cast<const H24*>(dr + bm);
            if (((unsigned)(p - 1) < 8u) && ((unsigned)(r - 1) < 8u))
                *reinterpret_cast<H24*>(sdr + ((p - 1) * 8 + (r - 1)) * 128 + x4) = q;
            float lf, rt;
            xhalo(c, tx, lf, rt);
            m = fk_point(c, ymv, ypv, zmv, zpv, lf, rt, q);
        } else {
            m = zero4;
            if ((unsigned)gy < W && (unsigned)gz < W) {
                const float4 c   = f4ld(usrc + bm);
                const float4 ymv = (gy > 0)     ? f4ld(usrc + bm - W)  : zero4;
                const float4 ypv = (gy < W - 1) ? f4ld(usrc + bm + W)  : zero4;
                const float4 zmv = (gz > 0)     ? f4ld(usrc + bm - PL) : zero4;
                const float4 zpv = (gz < W - 1) ? f4ld(usrc + bm + PL) : zero4;
                const H24 q = *reinterpret_cast<const H24*>(dr + bm);
                if (((unsigned)(p - 1) < 8u) && ((unsigned)(r - 1) < 8u))
                    *reinterpret_cast<H24*>(sdr + ((p - 1) * 8 + (r - 1)) * 128 + x4) = q;
                float lf, rt;
                xhalo(c, tx, lf, rt);
                m = fk_point(c, ymv, ypv, zmv, zpv, lf, rt, q);
            }
        }
        f4st(smid + (p * 10 + r) * 128 + x4, m);
    }
}

// Phase 2: pure smem reads (mids + dr) -> gmem stores.
__device__ __forceinline__ void pair_phase2(
    const float* __restrict__ smid,
    float* __restrict__ udst, float* __restrict__ uout,
    size_t bb, int y0, int zb, int tx, int ty, int tz, int x4, bool fin)
{
    const size_t PL = (size_t)W * W;
    const float* sdr = smid + SM_MID_FLOATS;
    const int y = y0 + ty;
    const int r_s = ty + 1;
    size_t g = bb + ((size_t)(zb + tz * 4) * W + y) * W + x4;
    #pragma unroll
    for (int dz = 0; dz < 4; ++dz) {
        const int zo  = tz * 4 + dz;              // 0..7 local
        const int p_s = zo + 1;
        const float* pc = smid + (p_s * 10 + r_s) * 128;
        const float4 c  = f4ld(pc + x4);
        const float4 ym = f4ld(smid + (p_s * 10 + r_s - 1) * 128 + x4);
        const float4 yp = f4ld(smid + (p_s * 10 + r_s + 1) * 128 + x4);
        const float4 zm = f4ld(smid + ((p_s - 1) * 10 + r_s) * 128 + x4);
        const float4 zp = f4ld(smid + ((p_s + 1) * 10 + r_s) * 128 + x4);
        const H24 q = *reinterpret_cast<const H24*>(sdr + (zo * 8 + ty) * 128 + x4);

        float lf, rt;
        xhalo(c, tx, lf, rt);
        float4 o = fk_point(c, ym, yp, zm, zp, lf, rt, q);

        if (fin) *reinterpret_cast<float4*>(uout + g) = clip01(o);
        else     *reinterpret_cast<float4*>(udst + g) = o;
        g += PL;
    }
}

// ---- pairs 1..19 ----
__global__ __launch_bounds__(512, 2)
void fk_pair(const float* __restrict__ usrc,
             float* __restrict__ udst,
             float* __restrict__ uout,
             const __half2* __restrict__ dr,
             const int* __restrict__ dt_days,
             int pair)
{
#if __CUDA_ARCH__ >= 900
    cudaTriggerProgrammaticLaunchCompletion();
#endif
    const int b  = blockIdx.z;
    const int dt = __ldg(dt_days + b);
    if (pair >= PPD * dt) return;               // CTA-uniform early exit
    const bool fin = (pair == PPD * dt - 1);

    const int tx = threadIdx.x, ty = threadIdx.y, tz = threadIdx.z;
    const int y0 = blockIdx.y * 8;
    const int zb = blockIdx.x * 8;
    const int x4 = tx << 2;
    const size_t bb = (size_t)b * VOL;
    const int tid16 = tz * 8 + ty;

    extern __shared__ float smid[];             // mids [10p][10r][128] + dr
    float* sdr = smid + SM_MID_FLOATS;

#if __CUDA_ARCH__ >= 900
    cudaGridDependencySynchronize();
#endif

    // CTA-uniform interior test: footprint [y0-1,y0+8]x[zb-1,zb+8] in range.
    if ((y0 > 0) & (y0 < W - 8) & (zb > 0) & (zb < W - 8))
        pair_phase1<true >(usrc, dr, smid, sdr, bb, y0, zb, tx, tid16, x4);
    else
        pair_phase1<false>(usrc, dr, smid, sdr, bb, y0, zb, tx, tid16, x4);

    __syncthreads();                             // the ONLY barrier

    pair_phase2(smid, udst, uout, bb, y0, zb, tx, ty, tz, x4, fin);
}

// ---- pair 0: reads fp32 u_t0 + D/rho, packs g_dr in phase 1 ----
__global__ __launch_bounds__(512, 2)
void fk_pair0(const float* __restrict__ usrc,
              float* __restrict__ udst,
              const float* __restrict__ Dm,
              const float* __restrict__ Rm,
              __half2* __restrict__ dr,
              const int* __restrict__ dt_days)
{
#if __CUDA_ARCH__ >= 900
    cudaTriggerProgrammaticLaunchCompletion();
#endif
    const int b  = blockIdx.z;
    const int dt = __ldg(dt_days + b);
    if (dt <= 0) return;                         // pair 0 active iff dt>=1
    // fin would need 5*dt == 1: impossible -> pair 0 never writes d_out.

    const int tx = threadIdx.x, ty = threadIdx.y, tz = threadIdx.z;
    const int y0 = blockIdx.y * 8;
    const int zb = blockIdx.x * 8;
    const int x4 = tx << 2;
    const size_t PL = (size_t)W * W;
    const size_t bb = (size_t)b * VOL;

    extern __shared__ float smid[];
    float* sdr = smid + SM_MID_FLOATS;

    const float4 zero4 = make_float4(0.f, 0.f, 0.f, 0.f);

    const int tid16 = tz * 8 + ty;
    for (int idx = tid16; idx < 100; idx += 16) {
        const int p = idx / 10;
        const int r = idx - p * 10;
        const int gy = y0 - 1 + r;
        const int gz = zb - 1 + p;
        float4 m = zero4;
        if ((unsigned)gy < W && (unsigned)gz < W) {
            const size_t bm = bb + ((size_t)gz * W + gy) * W + x4;
            const float4 c   = f4ld(usrc + bm);
            const float4 ymv = (gy > 0)     ? f4ld(usrc + bm - W)  : zero4;
            const float4 ypv = (gy < W - 1) ? f4ld(usrc + bm + W)  : zero4;
            const float4 zmv = (gz > 0)     ? f4ld(usrc + bm - PL) : zero4;
            const float4 zpv = (gz < W - 1) ? f4ld(usrc + bm + PL) : zero4;
            const float4 dv  = f4ld(Dm + bm);
            const float4 rv  = f4ld(Rm + bm);
            const H24 q = pack_dr(dv, rv);
            *reinterpret_cast<H24*>(dr + bm) = q;   // persist for later pairs
            if (((unsigned)(p - 1) < 8u) && ((unsigned)(r - 1) < 8u))
                *reinterpret_cast<H24*>(sdr + ((p - 1) * 8 + (r - 1)) * 128 + x4) = q;
            float lf, rt;
            xhalo(c, tx, lf, rt);
            m = fk_point(c, ymv, ypv, zmv, zpv, lf, rt, q);
        }
        f4st(smid + (p * 10 + r) * 128 + x4, m);
    }

    __syncthreads();

    pair_phase2(smid, udst, nullptr, bb, y0, zb, tx, ty, tz, x4, false);
}

// dt==0 batches: clipped copy of u_t0 -> d_out (independent; no gridsync).
__global__ __launch_bounds__(512)
void fk_tail(const float* __restrict__ u0,
             float* __restrict__ out,
             const int* __restrict__ dt_days)
{
#if __CUDA_ARCH__ >= 900
    cudaTriggerProgrammaticLaunchCompletion();
#endif
    const int b = blockIdx.z >> 5;
    if (__ldg(dt_days + b) != 0) return;

    const int x4 = threadIdx.x << 2;
    const int y  = blockIdx.y * 4 + threadIdx.y;
    const int z  = (blockIdx.z & 31) * 4 + threadIdx.z;
    const size_t base = (((size_t)b * W + z) * W + y) * W + x4;

    float4 v = f4ld(u0 + base);
    *reinterpret_cast<float4*>(out + base) = clip01(v);
}

extern "C" void kernel_launch(void* const* d_in, const int* in_sizes, int n_in,
                              void* d_out, int out_size)
{
    const float* u_t0    = (const float*)d_in[0];
    const float* D_map   = (const float*)d_in[1];
    const float* rho_map = (const float*)d_in[2];
    const int*   dt_days = (const int*)  d_in[3];
    float*       out     = (float*)d_out;

    float *p0 = nullptr, *p1 = nullptr;
    __half2* dr = nullptr;
    cudaGetSymbolAddress((void**)&p0, g_buf0);
    cudaGetSymbolAddress((void**)&p1, g_buf1);
    cudaGetSymbolAddress((void**)&dr, g_dr);
    float* bufs[2] = { p0, p1 };

    cudaFuncSetAttribute(fk_pair,  cudaFuncAttributeMaxDynamicSharedMemorySize,
                         SMEM_BYTES);
    cudaFuncSetAttribute(fk_pair0, cudaFuncAttributeMaxDynamicSharedMemorySize,
                         SMEM_BYTES);

    cudaLaunchAttribute attrs[1];
    attrs[0].id = cudaLaunchAttributeProgrammaticStreamSerialization;
    attrs[0].val.programmaticStreamSerializationAllowed = 1;

    cudaLaunchConfig_t cfg = {};
    cfg.gridDim = dim3(W / 8, W / 8, BATCH);     // (16, 16, 2) = 512 CTAs
    cfg.blockDim = dim3(32, 8, 2);               // 512 threads
    cfg.dynamicSmemBytes = SMEM_BYTES;
    cfg.stream = 0;
    cfg.attrs = attrs;
    cfg.numAttrs = 1;

    // Pair 0: fused dr packing + micro-steps 0,1.  Writes bufs[0].
    cudaLaunchKernelEx(&cfg, fk_pair0, u_t0, bufs[0], D_map, rho_map,
                       (__half2*)dr, dt_days);

    // Pairs 1..19: reads bufs[(p+1)&1], writes bufs[p&1].
    for (int p = 1; p < NPAIRS; ++p) {
        const float* src = bufs[(p + 1) & 1];
        float*       dst = bufs[p & 1];
        cudaLaunchKernelEx(&cfg, fk_pair, src, dst, out,
                           (const __half2*)dr, dt_days, p);
    }

    // Tail for dt==0 batches (fully overlappable).
    cudaLaunchConfig_t tcfg = cfg;
    tcfg.gridDim = dim3(1, W / 4, (W / 4) * BATCH);
    tcfg.blockDim = dim3(32, 4, 4);
    tcfg.dynamicSmemBytes = 0;
    cudaLaunchKernelEx(&tcfg, fk_tail, u_t0, out, dt_days);

    (void)in_sizes; (void)n_in; (void)out_size;
}

// round 17
// speedup vs baseline: 1.6249x; 1.6249x over previous
#include <cuda_runtime.h>
#include <cuda_fp16.h>

// Fisher-Kolmogorov rollout. R17 = R15 (one-barrier fused step-pair, dr in
// smem, fp16 {D,rho}, PDL, pair0 packs dr) + 32-bit offset arithmetic and
// division-free phase-1 indexing. No structural changes vs R15.

#define W        128
#define BATCH    2
#define SUBSTEPS 10
#define MAX_DAYS 4
#define NPAIRS   (SUBSTEPS * MAX_DAYS / 2)   // 20
#define PPD      (SUBSTEPS / 2)              // 5 pairs per day
#define MICRO_DT 0.1f

#define VOL  ((size_t)W * W * W)
#define NTOT (BATCH * VOL)

// smem: mids 100 rows x 512B, then dr 64 rows x 512B
#define SM_MID_FLOATS (100 * 128)
#define SMEM_BYTES    ((100 + 64) * 128 * 4)   // 83968

#define PL32 (W * W)                           // 16384 (fits int)

__device__ float g_buf0[NTOT];
__device__ float g_buf1[NTOT];
__device__ __half2 g_dr[NTOT];               // {D, rho} per point (16 MB)

struct __align__(16) H24 { __half2 h[4]; };

__device__ __forceinline__ float4 f4ld(const float* p) {
    return *reinterpret_cast<const float4*>(p);
}
__device__ __forceinline__ void f4st(float* p, float4 v) {
    *reinterpret_cast<float4*>(p) = v;
}

__device__ __forceinline__ void fk_comp(float& o, float c, float nb2,
                                        float nb4, __half2 drh)
{
    const float2 d2 = __half22float2(drh);    // x=D, y=rho
    const float lap = nb2 + nb4 - 6.0f * c;
    o = c + MICRO_DT * (d2.x * lap + d2.y * c * (1.0f - c));
}

__device__ __forceinline__ float4 fk_point(float4 c, float4 ym, float4 yp,
                                           float4 zm, float4 zp,
                                           float lf, float rt, H24 q)
{
    float4 o;
    fk_comp(o.x, c.x, lf  + c.y, ym.x + yp.x + zm.x + zp.x, q.h[0]);
    fk_comp(o.y, c.y, c.x + c.z, ym.y + yp.y + zm.y + zp.y, q.h[1]);
    fk_comp(o.z, c.z, c.y + c.w, ym.z + yp.z + zm.z + zp.z, q.h[2]);
    fk_comp(o.w, c.w, c.z + rt,  ym.w + yp.w + zm.w + zp.w, q.h[3]);
    return o;
}

__device__ __forceinline__ float4 clip01(float4 v)
{
    v.x = fminf(fmaxf(v.x, 0.f), 1.f);
    v.y = fminf(fmaxf(v.y, 0.f), 1.f);
    v.z = fminf(fmaxf(v.z, 0.f), 1.f);
    v.w = fminf(fmaxf(v.w, 0.f), 1.f);
    return v;
}

__device__ __forceinline__ H24 pack_dr(float4 d, float4 r)
{
    H24 q;
    q.h[0] = __floats2half2_rn(d.x, r.x);
    q.h[1] = __floats2half2_rn(d.y, r.y);
    q.h[2] = __floats2half2_rn(d.z, r.z);
    q.h[3] = __floats2half2_rn(d.w, r.w);
    return q;
}

__device__ __forceinline__ void xhalo(float4 u, int tx, float& lf, float& rt)
{
    lf = __shfl_up_sync(0xffffffffu, u.w, 1);
    rt = __shfl_down_sync(0xffffffffu, u.x, 1);
    if (tx == 0)  lf = 0.f;
    if (tx == 31) rt = 0.f;
}

// Phase 2: pure smem reads (mids + dr) -> gmem stores. 32-bit offsets.
__device__ __forceinline__ void pair_phase2(
    const float* __restrict__ smid,
    float* __restrict__ db, float* __restrict__ ob,   // batch-based pointers
    int y0, int zb, int tx, int ty, int tz, int x4, bool fin)
{
    const float* sdr = smid + SM_MID_FLOATS;
    const int y = y0 + ty;
    const int r_s = ty + 1;
    unsigned g = (unsigned)((zb + tz * 4) * W + y) * W + x4;
    #pragma unroll
    for (int dz = 0; dz < 4; ++dz) {
        const int zo  = tz * 4 + dz;              // 0..7 local
        const int p_s = zo + 1;
        const float* pc = smid + (p_s * 10 + r_s) * 128;
        const float4 c  = f4ld(pc + x4);
        const float4 ym = f4ld(pc - 128 + x4);
        const float4 yp = f4ld(pc + 128 + x4);
        const float4 zm = f4ld(pc - 1280 + x4);
        const float4 zp = f4ld(pc + 1280 + x4);
        const H24 q = *reinterpret_cast<const H24*>(sdr + (zo * 8 + ty) * 128 + x4);

        float lf, rt;
        xhalo(c, tx, lf, rt);
        float4 o = fk_point(c, ym, yp, zm, zp, lf, rt, q);

        if (fin) *reinterpret_cast<float4*>(ob + g) = clip01(o);
        else     *reinterpret_cast<float4*>(db + g) = o;
        g += PL32;
    }
}

// ---- pairs 1..19: fp32 state, packed dr from gmem ----
__global__ __launch_bounds__(512, 2)
void fk_pair(const float* __restrict__ usrc,
             float* __restrict__ udst,
             float* __restrict__ uout,
             const __half2* __restrict__ dr,
             const int* __restrict__ dt_days,
             int pair)
{
#if __CUDA_ARCH__ >= 900
    cudaTriggerProgrammaticLaunchCompletion();
#endif
    const int b  = blockIdx.z;
    const int dt = __ldg(dt_days + b);
    if (pair >= PPD * dt) return;               // CTA-uniform early exit
    const bool fin = (pair == PPD * dt - 1);

    const int tx = threadIdx.x, ty = threadIdx.y, tz = threadIdx.z;
    const int y0 = blockIdx.y * 8;
    const int zb = blockIdx.x * 8;
    const int x4 = tx << 2;

    // batch-based pointers: all further addressing is 32-bit
    const size_t bb = (size_t)b * VOL;
    const float*   ub  = usrc + bb;
    float*         db  = udst + bb;
    float*         ob  = uout + bb;
    const __half2* drb = dr + bb;

    extern __shared__ float smid[];             // mids [10p][10r][128] + dr
    float* sdr = smid + SM_MID_FLOATS;

#if __CUDA_ARCH__ >= 900
    cudaGridDependencySynchronize();
#endif

    const float4 zero4 = make_float4(0.f, 0.f, 0.f, 0.f);

    // Phase 1: 16 row-groups compute 100 mid rows; stash interior dr.
    // Division-free (p, r) carried across iterations.
    const int tid16 = tz * 8 + ty;
    int p = (tid16 >= 10) ? 1 : 0;
    int r = tid16 - p * 10;
    for (int idx = tid16; idx < 100; idx += 16) {
        const int gy = y0 - 1 + r;
        const int gz = zb - 1 + p;
        float4 m = zero4;
        if ((unsigned)gy < W && (unsigned)gz < W) {
            const unsigned bm = (unsigned)(gz * W + gy) * W + x4;
            const float4 c   = f4ld(ub + bm);
            const float4 ymv = (gy > 0)     ? f4ld(ub + bm - W)    : zero4;
            const float4 ypv = (gy < W - 1) ? f4ld(ub + bm + W)    : zero4;
            const float4 zmv = (gz > 0)     ? f4ld(ub + bm - PL32) : zero4;
            const float4 zpv = (gz < W - 1) ? f4ld(ub + bm + PL32) : zero4;
            const H24 q = *reinterpret_cast<const H24*>(drb + bm);
            if (((unsigned)(p - 1) < 8u) && ((unsigned)(r - 1) < 8u))
                *reinterpret_cast<H24*>(sdr + ((p - 1) * 8 + (r - 1)) * 128 + x4) = q;
            float lf, rt;
            xhalo(c, tx, lf, rt);
            m = fk_point(c, ymv, ypv, zmv, zpv, lf, rt, q);
        }
        f4st(smid + (p * 10 + r) * 128 + x4, m);
        // idx += 16  =>  p += 1, r += 6 (carry)
        p += 1; r += 6;
        if (r >= 10) { r -= 10; p += 1; }
    }

    __syncthreads();                             // the ONLY barrier

    pair_phase2(smid, db, ob, y0, zb, tx, ty, tz, x4, fin);
}

// ---- pair 0: reads fp32 u_t0 + D/rho, packs g_dr in phase 1 ----
__global__ __launch_bounds__(512, 2)
void fk_pair0(const float* __restrict__ usrc,
              float* __restrict__ udst,
              const float* __restrict__ Dm,
              const float* __restrict__ Rm,
              __half2* __restrict__ dr,
              const int* __restrict__ dt_days)
{
#if __CUDA_ARCH__ >= 900
    cudaTriggerProgrammaticLaunchCompletion();
#endif
    const int b  = blockIdx.z;
    const int dt = __ldg(dt_days + b);
    if (dt <= 0) return;                         // pair 0 active iff dt>=1
    // fin would need 5*dt == 1: impossible -> pair 0 never writes d_out.

    const int tx = threadIdx.x, ty = threadIdx.y, tz = threadIdx.z;
    const int y0 = blockIdx.y * 8;
    const int zb = blockIdx.x * 8;
    const int x4 = tx << 2;

    const size_t bb = (size_t)b * VOL;
    const float* ub  = usrc + bb;
    float*       db  = udst + bb;
    const float* Db  = Dm + bb;
    const float* Rb  = Rm + bb;
    __half2*     drb = dr + bb;

    extern __shared__ float smid[];
    float* sdr = smid + SM_MID_FLOATS;

    const float4 zero4 = make_float4(0.f, 0.f, 0.f, 0.f);

    const int tid16 = tz * 8 + ty;
    int p = (tid16 >= 10) ? 1 : 0;
    int r = tid16 - p * 10;
    for (int idx = tid16; idx < 100; idx += 16) {
        const int gy = y0 - 1 + r;
        const int gz = zb - 1 + p;
        float4 m = zero4;
        if ((unsigned)gy < W && (unsigned)gz < W) {
            const unsigned bm = (unsigned)(gz * W + gy) * W + x4;
            const float4 c   = f4ld(ub + bm);
            const float4 ymv = (gy > 0)     ? f4ld(ub + bm - W)    : zero4;
            const float4 ypv = (gy < W - 1) ? f4ld(ub + bm + W)    : zero4;
            const float4 zmv = (gz > 0)     ? f4ld(ub + bm - PL32) : zero4;
            const float4 zpv = (gz < W - 1) ? f4ld(ub + bm + PL32) : zero4;
            const float4 dv  = f4ld(Db + bm);
            const float4 rv  = f4ld(Rb + bm);
            const H24 q = pack_dr(dv, rv);
            *reinterpret_cast<H24*>(drb + bm) = q;   // persist for later pairs
            if (((unsigned)(p - 1) < 8u) && ((unsigned)(r - 1) < 8u))
                *reinterpret_cast<H24*>(sdr + ((p - 1) * 8 + (r - 1)) * 128 + x4) = q;
            float lf, rt;
            xhalo(c, tx, lf, rt);
            m = fk_point(c, ymv, ypv, zmv, zpv, lf, rt, q);
        }
        f4st(smid + (p * 10 + r) * 128 + x4, m);
        p += 1; r += 6;
        if (r >= 10) { r -= 10; p += 1; }
    }

    __syncthreads();

    pair_phase2(smid, db, nullptr, y0, zb, tx, ty, tz, x4, false);
}

// dt==0 batches: clipped copy of u_t0 -> d_out (independent; no gridsync).
__global__ __launch_bounds__(512)
void fk_tail(const float* __restrict__ u0,
             float* __restrict__ out,
             const int* __restrict__ dt_days)
{
#if __CUDA_ARCH__ >= 900
    cudaTriggerProgrammaticLaunchCompletion();
#endif
    const int b = blockIdx.z >> 5;
    if (__ldg(dt_days + b) != 0) return;

    const int x4 = threadIdx.x << 2;
    const int y  = blockIdx.y * 4 + threadIdx.y;
    const int z  = (blockIdx.z & 31) * 4 + threadIdx.z;
    const size_t base = (((size_t)b * W + z) * W + y) * W + x4;

    float4 v = f4ld(u0 + base);
    *reinterpret_cast<float4*>(out + base) = clip01(v);
}

extern "C" void kernel_launch(void* const* d_in, const int* in_sizes, int n_in,
                              void* d_out, int out_size)
{
    const float* u_t0    = (const float*)d_in[0];
    const float* D_map   = (const float*)d_in[1];
    const float* rho_map = (const float*)d_in[2];
    const int*   dt_days = (const int*)  d_in[3];
    float*       out     = (float*)d_out;

    float *p0 = nullptr, *p1 = nullptr;
    __half2* dr = nullptr;
    cudaGetSymbolAddress((void**)&p0, g_buf0);
    cudaGetSymbolAddress((void**)&p1, g_buf1);
    cudaGetSymbolAddress((void**)&dr, g_dr);
    float* bufs[2] = { p0, p1 };

    cudaFuncSetAttribute(fk_pair,  cudaFuncAttributeMaxDynamicSharedMemorySize,
                         SMEM_BYTES);
    cudaFuncSetAttribute(fk_pair0, cudaFuncAttributeMaxDynamicSharedMemorySize,
                         SMEM_BYTES);

    cudaLaunchAttribute attrs[1];
    attrs[0].id = cudaLaunchAttributeProgrammaticStreamSerialization;
    attrs[0].val.programmaticStreamSerializationAllowed = 1;

    cudaLaunchConfig_t cfg = {};
    cfg.gridDim = dim3(W / 8, W / 8, BATCH);     // (16, 16, 2) = 512 CTAs
    cfg.blockDim = dim3(32, 8, 2);               // 512 threads
    cfg.dynamicSmemBytes = SMEM_BYTES;
    cfg.stream = 0;
    cfg.attrs = attrs;
    cfg.numAttrs = 1;

    // Pair 0: fused dr packing + micro-steps 0,1.  Writes bufs[0].
    cudaLaunchKernelEx(&cfg, fk_pair0, u_t0, bufs[0], D_map, rho_map,
                       (__half2*)dr, dt_days);

    // Pairs 1..19: reads bufs[(p+1)&1], writes bufs[p&1].
    for (int p = 1; p < NPAIRS; ++p) {
        const float* src = bufs[(p + 1) & 1];
        float*       dst = bufs[p & 1];
        cudaLaunchKernelEx(&cfg, fk_pair, src, dst, out,
                           (const __half2*)dr, dt_days, p);
    }

    // Tail for dt==0 batches (fully overlappable).
    cudaLaunchConfig_t tcfg = cfg;
    tcfg.gridDim = dim3(1, W / 4, (W / 4) * BATCH);
    tcfg.blockDim = dim3(32, 4, 4);
    tcfg.dynamicSmemBytes = 0;
    cudaLaunchKernelEx(&tcfg, fk_tail, u_t0, out, dt_days);

    (void)in_sizes; (void)n_in; (void)out_size;
}